// round 11
// baseline (speedup 1.0000x reference)
#include <cuda_runtime.h>

#define N_IMG 8
#define H 32
#define W 32
#define CIN 32
#define COUT 64
#define HO 30
#define WO 30
#define NPIX (N_IMG*HO*WO)       // 7200
#define PDIM (3*3*CIN)           // 288
#define HW (H*W)

typedef unsigned long long u64;
typedef unsigned int u32;

// Scratch (device globals: no allocation allowed in kernel_launch)
// g_vq: NCHW quad layout: [(n*CIN+ci)*H + h]*W + w -> {vp,vp,vn,vn} (16B)
__device__ __align__(16) float4 g_vq[N_IMG*CIN*H*W];
// Paired-transposed weights: g_ekt[P*32 + c2] (P = ci-pair row 0..143, c2 =
// cout-pair 0..31): .x = f32x2 {ek[2P][2c2], ek[2P][2c2+1]},
//                   .y = f32x2 {ek[2P+1][2c2], ek[2P+1][2c2+1]}
__device__ __align__(16) ulonglong2 g_ekt1[(PDIM/2)*(COUT/2)];
__device__ __align__(16) ulonglong2 g_ekt2[(PDIM/2)*(COUT/2)];

#define TBLOCKS (N_IMG*H)        // 256 transpose blocks
#define NWPAIR ((PDIM/2)*(COUT/2))          // 4608
#define WBLOCKS ((NWPAIR + 1023)/1024)      // 5

// Two packed f32x2 multiplies, fold both products into each u32 accumulator
// with one 3-input DPX max. Valid: all products are strictly positive finite
// floats (v >= 0.1, w = exp(k) > 0); positive IEEE floats order like u32.
__device__ __forceinline__ void mm3(u64 v0, u64 w0, u64 v1, u64 w1,
                                    u32& a0, u32& a1) {
    u32 p0lo, p0hi, p1lo, p1hi;
    asm("{\n\t"
        ".reg .b64 t0, t1;\n\t"
        "mul.rn.f32x2 t0, %4, %5;\n\t"
        "mul.rn.f32x2 t1, %6, %7;\n\t"
        "mov.b64 {%0, %1}, t0;\n\t"
        "mov.b64 {%2, %3}, t1;\n\t"
        "}"
        : "=r"(p0lo), "=r"(p0hi), "=r"(p1lo), "=r"(p1hi)
        : "l"(v0), "l"(w0), "l"(v1), "l"(w1));
    a0 = __vimax3_u32(a0, p0lo, p1lo);
    a1 = __vimax3_u32(a1, p0hi, p1hi);
}

__device__ __forceinline__ u64 packf2(float lo, float hi) {
    return (u64)__float_as_uint(lo) | ((u64)__float_as_uint(hi) << 32);
}

// ---------------------------------------------------------------------------
// Fused prep:
//   blocks [0,TBLOCKS): clamp + NHWC -> NCHW-quad transpose via smem tile
//   blocks [TBLOCKS,+WBLOCKS): exp(weights) into paired-transposed layout
// ---------------------------------------------------------------------------
__global__ void prep(const float* __restrict__ x,
                     const float* __restrict__ k1,
                     const float* __restrict__ k2) {
    const int b = blockIdx.x;
    if (b < TBLOCKS) {
        __shared__ float tile[32][33];
        const int n = b >> 5;
        const int h = b & 31;
        {
            const int c = threadIdx.x;   // contiguous in gmem -> coalesced read
            const int w = threadIdx.y;
            tile[w][c] = x[(((n*H + h)*W + w)*CIN) + c];
        }
        __syncthreads();
        {
            const int w = threadIdx.x;   // contiguous in output -> coalesced write
            const int c = threadIdx.y;
            const float v  = tile[w][c];
            const float vp = fmaxf(v, 0.1f);
            const float vn = fmaxf(-v, 0.1f);
            g_vq[((n*CIN + c)*H + h)*W + w] = make_float4(vp, vp, vn, vn);
        }
    } else {
        const int tid = (b - TBLOCKS)*1024 + threadIdx.y*32 + threadIdx.x;
        if (tid < NWPAIR) {
            const int P  = tid >> 5;     // ci-pair row
            const int c2 = tid & 31;     // cout pair
            const int base = (2*P)*COUT + 2*c2;
            ulonglong2 e1, e2;
            e1.x = packf2(expf(k1[base]),        expf(k1[base+1]));
            e1.y = packf2(expf(k1[base+COUT]),   expf(k1[base+COUT+1]));
            e2.x = packf2(expf(k2[base]),        expf(k2[base+1]));
            e2.y = packf2(expf(k2[base+COUT]),   expf(k2[base+COUT+1]));
            g_ekt1[tid] = e1;
            g_ekt2[tid] = e2;
        }
    }
}

// ---------------------------------------------------------------------------
// Main: CTA = 128 thr = 4 warps; warp = 4 pixels x 16 couts (2 couts/lane).
//   lane: cg = l&7 (cout pair), ps = l>>3 (pixel 0..3)
//   warp wrp covers cout-16-group wrp; CTA covers 4 px x 64 couts.
//   grid = 1800 CTAs -> ~12.2 CTAs/SM, 48 warps/SM resident (regs <= 42).
// Per 2-ci iter per lane: 2 v LDG.128 (broadcast over cg) + 2 w LDG.128
//   (1 wavefront each: 8 cg-lanes x 16B contiguous) + 8 MUL.f32x2
//   + 8 VIMNMX3  ->  ~23 slots / 512 products per warp.
// No smem, no sync, 8 u32 accumulators per lane.
// ---------------------------------------------------------------------------
__global__ void __launch_bounds__(128, 12)
morph_main(const float* __restrict__ bias, float* __restrict__ out) {
    const int l   = threadIdx.x & 31;
    const int g16 = threadIdx.x >> 5;   // cout-16 group 0..3
    const int cg  = l & 7;              // cout pair within group
    const int ps  = l >> 3;             // pixel slot 0..3
    const int c0  = g16*16 + cg*2;

    const int q  = blockIdx.x*4 + ps;   // flat pixel 0..7199
    const int n  = q / (HO*WO);
    const int r  = q - n*(HO*WO);
    const int ho = r / WO;
    const int wo = r - ho*WO;

    // NCHW quads: (ci, ho+i, wo+j) at vbase + ci*HW + i*W + j
    const ulonglong2* __restrict__ vbase =
        reinterpret_cast<const ulonglong2*>(g_vq) + (n*CIN*H + ho)*W + wo;
    const ulonglong2* __restrict__ w1p = g_ekt1 + g16*8 + cg;
    const ulonglong2* __restrict__ w2p = g_ekt2 + g16*8 + cg;

    u32 m11a=0u, m11b=0u, m12a=0u, m12b=0u;
    u32 m21a=0u, m21b=0u, m22a=0u, m22b=0u;

    #pragma unroll 1
    for (int ij = 0; ij < 9; ij++) {
        const int i = ij / 3;
        const int j = ij - 3*i;
        const ulonglong2* __restrict__ vp = vbase + i*W + j;
        const ulonglong2* __restrict__ a1 = w1p + (ij*16)*32;
        const ulonglong2* __restrict__ a2 = w2p + (ij*16)*32;

        #pragma unroll 4
        for (int c2 = 0; c2 < 16; c2++) {
            const ulonglong2 va = __ldg(vp + (2*c2)*HW);     // {vxx, vyy} ci
            const ulonglong2 vb = __ldg(vp + (2*c2+1)*HW);   // {vxx, vyy} ci+1
            const ulonglong2 w1 = __ldg(a1 + c2*32);         // {pair ci, pair ci+1}
            const ulonglong2 w2 = __ldg(a2 + c2*32);
            mm3(va.x, w1.x, vb.x, w1.y, m11a, m11b);
            mm3(va.x, w2.x, vb.x, w2.y, m12a, m12b);
            mm3(va.y, w1.x, vb.y, w1.y, m21a, m21b);
            mm3(va.y, w2.x, vb.y, w2.y, m22a, m22b);
        }
    }

    const float2 bv = *reinterpret_cast<const float2*>(bias + c0);
    float2 res;
    res.x = __uint_as_float(m11a) - __uint_as_float(m12a)
          - __uint_as_float(m21a) + __uint_as_float(m22a) + bv.x;
    res.y = __uint_as_float(m11b) - __uint_as_float(m12b)
          - __uint_as_float(m21b) + __uint_as_float(m22b) + bv.y;

    *reinterpret_cast<float2*>(out + (size_t)q*COUT + c0) = res;
}

// ---------------------------------------------------------------------------
extern "C" void kernel_launch(void* const* d_in, const int* in_sizes, int n_in,
                              void* d_out, int out_size) {
    const float* x    = (const float*)d_in[0];
    const float* k1   = (const float*)d_in[1];
    const float* k2   = (const float*)d_in[2];
    const float* bias = (const float*)d_in[3];
    float* out = (float*)d_out;

    prep<<<TBLOCKS + WBLOCKS, dim3(32,32)>>>(x, k1, k2);
    morph_main<<<NPIX/4, 128>>>(bias, out);
}

// round 12
// speedup vs baseline: 1.6609x; 1.6609x over previous
#include <cuda_runtime.h>

#define N_IMG 8
#define H 32
#define W 32
#define CIN 32
#define COUT 64
#define HO 30
#define WO 30
#define NPIX (N_IMG*HO*WO)       // 7200
#define PDIM (3*3*CIN)           // 288

typedef unsigned long long u64;
typedef unsigned int u32;

// ---------------------------------------------------------------------------
// Device-global scratch (no allocation allowed in kernel_launch)
// g_v: [n*H + h][ci][w] float2 {max(x,.1), max(-x,.1)}  (8KB per (n,h) slab)
// g_wp: packed weight pairs, [half][k][cg][t] ulonglong2:
//   t=0: { f32x2{ek1[k][c0],ek1[k][c0+1]}, f32x2{ek1[k][c0+2],ek1[k][c0+3]} }
//   t=1: same for ek2.   c0 = half*32 + cg*4,  k = 0..287, cg = 0..7
// ---------------------------------------------------------------------------
__device__ __align__(16) float2     g_v[N_IMG*H*CIN*W];
__device__ __align__(16) ulonglong2 g_wp[2*PDIM*8*2];     // 9216 entries

#define TBLOCKS (N_IMG*H)        // 256 transpose blocks
#define WITEMS  (2*PDIM*8)       // 4608 weight items
#define WBLOCKS ((WITEMS + 1023)/1024)  // 5

#define SW_ENTRIES (PDIM*8*2)    // 4608 ulonglong2 = 73728 B
#define SV_FLOAT2  (3*CIN*W + 4) // 3076 float2 (4 pad for j+px overread)
#define SMEM_BYTES (SW_ENTRIES*16 + SV_FLOAT2*8)   // 98336

// Two packed f32x2 multiplies, fold both products into each u32 accumulator
// with one 3-input DPX max. Valid: all products are strictly positive finite
// floats (v >= 0.1, w = exp(k) > 0); positive IEEE floats order like u32.
__device__ __forceinline__ void mm3(u64 v0, u64 w0, u64 v1, u64 w1,
                                    u32& a0, u32& a1) {
    u32 p0lo, p0hi, p1lo, p1hi;
    asm("{\n\t"
        ".reg .b64 t0, t1;\n\t"
        "mul.rn.f32x2 t0, %4, %5;\n\t"
        "mul.rn.f32x2 t1, %6, %7;\n\t"
        "mov.b64 {%0, %1}, t0;\n\t"
        "mov.b64 {%2, %3}, t1;\n\t"
        "}"
        : "=r"(p0lo), "=r"(p0hi), "=r"(p1lo), "=r"(p1hi)
        : "l"(v0), "l"(w0), "l"(v1), "l"(w1));
    a0 = __vimax3_u32(a0, p0lo, p1lo);
    a1 = __vimax3_u32(a1, p0hi, p1hi);
}

__device__ __forceinline__ u64 pack2(float lo, float hi) {
    u64 d; asm("mov.b64 %0, {%1, %2};" : "=l"(d) : "f"(lo), "f"(hi)); return d;
}
__device__ __forceinline__ u64 packh(float lo, float hi) {
    return (u64)__float_as_uint(lo) | ((u64)__float_as_uint(hi) << 32);
}

// ---------------------------------------------------------------------------
// Fused prep:
//   blocks [0,TBLOCKS): clamp + NHWC -> [n,h][ci][w] float2 transpose
//   blocks [TBLOCKS,+WBLOCKS): exp(weights) into packed-pair layout
// ---------------------------------------------------------------------------
__global__ void prep(const float* __restrict__ x,
                     const float* __restrict__ k1,
                     const float* __restrict__ k2) {
    const int b = blockIdx.x;
    if (b < TBLOCKS) {
        __shared__ float tile[32][33];
        const int n = b >> 5;
        const int h = b & 31;
        {
            const int c = threadIdx.x;   // coalesced read (ci contiguous)
            const int w = threadIdx.y;
            tile[w][c] = x[(((n*H + h)*W + w)*CIN) + c];
        }
        __syncthreads();
        {
            const int w = threadIdx.x;   // coalesced write (w contiguous)
            const int c = threadIdx.y;
            const float v = tile[w][c];
            g_v[((n*H + h)*CIN + c)*W + w] =
                make_float2(fmaxf(v, 0.1f), fmaxf(-v, 0.1f));
        }
    } else {
        const int item = (b - TBLOCKS)*1024 + threadIdx.y*32 + threadIdx.x;
        if (item < WITEMS) {
            const int half = item / (PDIM*8);
            const int rem  = item - half*(PDIM*8);
            const int k    = rem >> 3;
            const int cg   = rem & 7;
            const int c0   = half*32 + cg*4;
            const int base = k*COUT + c0;
            ulonglong2 e1, e2;
            e1.x = packh(expf(k1[base]),   expf(k1[base+1]));
            e1.y = packh(expf(k1[base+2]), expf(k1[base+3]));
            e2.x = packh(expf(k2[base]),   expf(k2[base+1]));
            e2.y = packh(expf(k2[base+2]), expf(k2[base+3]));
            g_wp[item*2]     = e1;
            g_wp[item*2 + 1] = e2;
        }
    }
}

// ---------------------------------------------------------------------------
// Main: CTA = 256 thr = 8 warps; blockIdx = (row 0..239) x (cout-half 0..1).
// Warp cg: 32 pixel-lanes (w positions of one output row) x 4 couts.
// Stage: 72KB weights (this half) + 24KB v (3 input rows) into smem once.
// Inner loop (2 ci per iter): 2 LDS.64 (v, conflict-free) + 4 LDS.128
//   (w, same-address broadcast) + 16 MUL.f32x2 + 16 VIMNMX3. Zero gmem.
// ---------------------------------------------------------------------------
__global__ void __launch_bounds__(256)
morph_main(const float* __restrict__ bias, float* __restrict__ out) {
    extern __shared__ __align__(16) char smem[];
    ulonglong2* s_w = reinterpret_cast<ulonglong2*>(smem);
    float2*     s_v = reinterpret_cast<float2*>(smem + SW_ENTRIES*16);

    const int tid  = threadIdx.x;
    const int cg   = tid >> 5;          // warp id = cout group (4 couts)
    const int px   = tid & 31;          // pixel lane (w position)
    const int row  = blockIdx.x >> 1;   // 0..239
    const int half = blockIdx.x & 1;
    const int n    = row / HO;
    const int ho   = row - n*HO;
    const int c0   = half*32 + cg*4;

    // Stage weights for this cout-half (contiguous 73728B)
    {
        const ulonglong2* __restrict__ src = g_wp + half*SW_ENTRIES;
        for (int idx = tid; idx < SW_ENTRIES; idx += 256)
            s_w[idx] = src[idx];
    }
    // Stage v rows ho..ho+2 (contiguous slabs: 1536 x 16B)
    {
        const ulonglong2* __restrict__ src =
            reinterpret_cast<const ulonglong2*>(g_v + (n*H + ho)*CIN*W);
        ulonglong2* dst = reinterpret_cast<ulonglong2*>(s_v);
        for (int idx = tid; idx < 3*CIN*W/2; idx += 256)
            dst[idx] = src[idx];
    }
    __syncthreads();

    u32 m11[4], m12[4], m21[4], m22[4];
    #pragma unroll
    for (int k = 0; k < 4; k++) { m11[k]=0u; m12[k]=0u; m21[k]=0u; m22[k]=0u; }

    const ulonglong2* __restrict__ wbase = s_w + cg*2;

    #pragma unroll 1
    for (int ij = 0; ij < 9; ij++) {
        const int i = ij / 3;
        const int j = ij - 3*i;
        // v for (row ho+i, ci, w = j+px): [ci][w] stride W, lanes contiguous
        const float2* __restrict__ vrow = s_v + i*(CIN*W) + j + px;
        const ulonglong2* __restrict__ wp = wbase + (ij*CIN)*16;

        #pragma unroll 8
        for (int ci = 0; ci < CIN; ci += 2) {
            const float2 va = vrow[ci*W];
            const float2 vb = vrow[(ci+1)*W];
            const ulonglong2 w1a = wp[ci*16];          // broadcast LDS.128
            const ulonglong2 w2a = wp[ci*16 + 1];
            const ulonglong2 w1b = wp[(ci+1)*16];
            const ulonglong2 w2b = wp[(ci+1)*16 + 1];
            const u64 vxa = pack2(va.x, va.x);
            const u64 vya = pack2(va.y, va.y);
            const u64 vxb = pack2(vb.x, vb.x);
            const u64 vyb = pack2(vb.y, vb.y);
            mm3(vxa, w1a.x, vxb, w1b.x, m11[0], m11[1]);
            mm3(vxa, w1a.y, vxb, w1b.y, m11[2], m11[3]);
            mm3(vxa, w2a.x, vxb, w2b.x, m12[0], m12[1]);
            mm3(vxa, w2a.y, vxb, w2b.y, m12[2], m12[3]);
            mm3(vya, w1a.x, vyb, w1b.x, m21[0], m21[1]);
            mm3(vya, w1a.y, vyb, w1b.y, m21[2], m21[3]);
            mm3(vya, w2a.x, vyb, w2b.x, m22[0], m22[1]);
            mm3(vya, w2a.y, vyb, w2b.y, m22[2], m22[3]);
        }
    }

    if (px < WO) {
        const int q = (n*HO + ho)*WO + px;
        const float4 bv = *reinterpret_cast<const float4*>(bias + c0);
        float4 res;
        res.x = __uint_as_float(m11[0]) - __uint_as_float(m12[0])
              - __uint_as_float(m21[0]) + __uint_as_float(m22[0]) + bv.x;
        res.y = __uint_as_float(m11[1]) - __uint_as_float(m12[1])
              - __uint_as_float(m21[1]) + __uint_as_float(m22[1]) + bv.y;
        res.z = __uint_as_float(m11[2]) - __uint_as_float(m12[2])
              - __uint_as_float(m21[2]) + __uint_as_float(m22[2]) + bv.z;
        res.w = __uint_as_float(m11[3]) - __uint_as_float(m12[3])
              - __uint_as_float(m21[3]) + __uint_as_float(m22[3]) + bv.w;
        *reinterpret_cast<float4*>(out + (size_t)q*COUT + c0) = res;
    }
}

// ---------------------------------------------------------------------------
extern "C" void kernel_launch(void* const* d_in, const int* in_sizes, int n_in,
                              void* d_out, int out_size) {
    const float* x    = (const float*)d_in[0];
    const float* k1   = (const float*)d_in[1];
    const float* k2   = (const float*)d_in[2];
    const float* bias = (const float*)d_in[3];
    float* out = (float*)d_out;

    // Idempotent attribute set (host-side, not a stream op; capture-safe).
    cudaFuncSetAttribute(morph_main,
                         cudaFuncAttributeMaxDynamicSharedMemorySize,
                         SMEM_BYTES);

    prep<<<TBLOCKS + WBLOCKS, dim3(32,32)>>>(x, k1, k2);
    morph_main<<<HO*N_IMG*2, 256, SMEM_BYTES>>>(bias, out);
}

// round 13
// speedup vs baseline: 1.7369x; 1.0458x over previous
#include <cuda_runtime.h>

#define N_IMG 8
#define H 32
#define W 32
#define CIN 32
#define COUT 64
#define HO 30
#define WO 30
#define NPIX (N_IMG*HO*WO)       // 7200
#define PDIM (3*3*CIN)           // 288

typedef unsigned long long u64;
typedef unsigned int u32;

// ---------------------------------------------------------------------------
// Device-global scratch (no allocation allowed in kernel_launch)
// g_v: [n*H + h][ci][w] float2 {max(x,.1), max(-x,.1)}
// g_wp: packed weight pairs, [half][k][cg][t] ulonglong2 (see R12)
// ---------------------------------------------------------------------------
__device__ __align__(16) float2     g_v[N_IMG*H*CIN*W];
__device__ __align__(16) ulonglong2 g_wp[2*PDIM*8*2];     // 9216 entries

#define TBLOCKS (N_IMG*H)        // 256 transpose blocks
#define WITEMS  (2*PDIM*8)       // 4608 weight items
#define WBLOCKS ((WITEMS + 1023)/1024)  // 5

#define SW_ENTRIES (PDIM*8*2)    // 4608 ulonglong2 = 73728 B
#define SV_FLOAT2  (3*CIN*W + 4) // 3076 float2 (4 pad for j+px overread)
#define SMEM_BYTES (SW_ENTRIES*16 + SV_FLOAT2*8)   // 98336

// Two packed f32x2 multiplies, fold both products into each u32 accumulator
// with one 3-input DPX max. Valid: all products are strictly positive finite
// floats (v >= 0.1, w = exp(k) > 0); positive IEEE floats order like u32.
__device__ __forceinline__ void mm3(u64 v0, u64 w0, u64 v1, u64 w1,
                                    u32& a0, u32& a1) {
    u32 p0lo, p0hi, p1lo, p1hi;
    asm("{\n\t"
        ".reg .b64 t0, t1;\n\t"
        "mul.rn.f32x2 t0, %4, %5;\n\t"
        "mul.rn.f32x2 t1, %6, %7;\n\t"
        "mov.b64 {%0, %1}, t0;\n\t"
        "mov.b64 {%2, %3}, t1;\n\t"
        "}"
        : "=r"(p0lo), "=r"(p0hi), "=r"(p1lo), "=r"(p1hi)
        : "l"(v0), "l"(w0), "l"(v1), "l"(w1));
    a0 = __vimax3_u32(a0, p0lo, p1lo);
    a1 = __vimax3_u32(a1, p0hi, p1hi);
}

__device__ __forceinline__ u64 pack2(float lo, float hi) {
    u64 d; asm("mov.b64 %0, {%1, %2};" : "=l"(d) : "f"(lo), "f"(hi)); return d;
}
__device__ __forceinline__ u64 packh(float lo, float hi) {
    return (u64)__float_as_uint(lo) | ((u64)__float_as_uint(hi) << 32);
}

// ---------------------------------------------------------------------------
// Fused prep:
//   blocks [0,TBLOCKS): clamp + NHWC -> [n,h][ci][w] float2 transpose
//   blocks [TBLOCKS,+WBLOCKS): exp(weights) into packed-pair layout
// ---------------------------------------------------------------------------
__global__ void prep(const float* __restrict__ x,
                     const float* __restrict__ k1,
                     const float* __restrict__ k2) {
    const int b = blockIdx.x;
    if (b < TBLOCKS) {
        __shared__ float tile[32][33];
        const int n = b >> 5;
        const int h = b & 31;
        {
            const int c = threadIdx.x;   // coalesced read (ci contiguous)
            const int w = threadIdx.y;
            tile[w][c] = x[(((n*H + h)*W + w)*CIN) + c];
        }
        __syncthreads();
        {
            const int w = threadIdx.x;   // coalesced write (w contiguous)
            const int c = threadIdx.y;
            const float v = tile[w][c];
            g_v[((n*H + h)*CIN + c)*W + w] =
                make_float2(fmaxf(v, 0.1f), fmaxf(-v, 0.1f));
        }
    } else {
        const int item = (b - TBLOCKS)*1024 + threadIdx.y*32 + threadIdx.x;
        if (item < WITEMS) {
            const int half = item / (PDIM*8);
            const int rem  = item - half*(PDIM*8);
            const int k    = rem >> 3;
            const int cg   = rem & 7;
            const int c0   = half*32 + cg*4;
            const int base = k*COUT + c0;
            ulonglong2 e1, e2;
            e1.x = packh(expf(k1[base]),   expf(k1[base+1]));
            e1.y = packh(expf(k1[base+2]), expf(k1[base+3]));
            e2.x = packh(expf(k2[base]),   expf(k2[base+1]));
            e2.y = packh(expf(k2[base+2]), expf(k2[base+3]));
            g_wp[item*2]     = e1;
            g_wp[item*2 + 1] = e2;
        }
    }
}

// ---------------------------------------------------------------------------
// Main: CTA = 512 thr = 16 warps; blockIdx = (row 0..239) x (cout-half 0..1).
// Warp wid: cg = wid&7 (4 couts), cihalf = wid>>3 (ci in [16*cihalf, +16)).
// Same 96KB smem as R12, but 2x the warps with half the work each ->
// 8 warps/SMSP instead of 4 to hide the 29-cyc LDS latency.
// After the loop, cihalf=1 warps publish accs into the (dead) v region;
// cihalf=0 warps max-combine + store.
// ---------------------------------------------------------------------------
__global__ void __launch_bounds__(512, 2)
morph_main(const float* __restrict__ bias, float* __restrict__ out) {
    extern __shared__ __align__(16) char smem[];
    ulonglong2* s_w = reinterpret_cast<ulonglong2*>(smem);
    float2*     s_v = reinterpret_cast<float2*>(smem + SW_ENTRIES*16);
    uint4*      s_r = reinterpret_cast<uint4*>(smem + SW_ENTRIES*16); // reuse

    const int tid    = threadIdx.x;
    const int wid    = tid >> 5;
    const int px     = tid & 31;
    const int cg     = wid & 7;          // cout group (4 couts)
    const int cihalf = wid >> 3;         // 0 or 1
    const int row    = blockIdx.x >> 1;  // 0..239
    const int half   = blockIdx.x & 1;
    const int n      = row / HO;
    const int ho     = row - n*HO;
    const int c0     = half*32 + cg*4;

    // Stage weights for this cout-half (contiguous 73728B)
    {
        const ulonglong2* __restrict__ src = g_wp + half*SW_ENTRIES;
        for (int idx = tid; idx < SW_ENTRIES; idx += 512)
            s_w[idx] = src[idx];
    }
    // Stage v rows ho..ho+2 (contiguous slabs: 1536 x 16B)
    {
        const ulonglong2* __restrict__ src =
            reinterpret_cast<const ulonglong2*>(g_v + (n*H + ho)*CIN*W);
        ulonglong2* dst = reinterpret_cast<ulonglong2*>(s_v);
        for (int idx = tid; idx < 3*CIN*W/2; idx += 512)
            dst[idx] = src[idx];
    }
    __syncthreads();

    u32 m11[4], m12[4], m21[4], m22[4];
    #pragma unroll
    for (int k = 0; k < 4; k++) { m11[k]=0u; m12[k]=0u; m21[k]=0u; m22[k]=0u; }

    const ulonglong2* __restrict__ wbase = s_w + cg*2;
    const int klo = cihalf*16;

    #pragma unroll 1
    for (int ij = 0; ij < 9; ij++) {
        const int i = ij / 3;
        const int j = ij - 3*i;
        const float2* __restrict__ vrow = s_v + i*(CIN*W) + klo*W + j + px;
        const ulonglong2* __restrict__ wp = wbase + (ij*CIN + klo)*16;

        #pragma unroll 4
        for (int ci = 0; ci < 16; ci += 2) {
            const float2 va = vrow[ci*W];
            const float2 vb = vrow[(ci+1)*W];
            const ulonglong2 w1a = wp[ci*16];          // broadcast LDS.128
            const ulonglong2 w2a = wp[ci*16 + 1];
            const ulonglong2 w1b = wp[(ci+1)*16];
            const ulonglong2 w2b = wp[(ci+1)*16 + 1];
            const u64 vxa = pack2(va.x, va.x);
            const u64 vya = pack2(va.y, va.y);
            const u64 vxb = pack2(vb.x, vb.x);
            const u64 vyb = pack2(vb.y, vb.y);
            mm3(vxa, w1a.x, vxb, w1b.x, m11[0], m11[1]);
            mm3(vxa, w1a.y, vxb, w1b.y, m11[2], m11[3]);
            mm3(vxa, w2a.x, vxb, w2b.x, m12[0], m12[1]);
            mm3(vxa, w2a.y, vxb, w2b.y, m12[2], m12[3]);
            mm3(vya, w1a.x, vyb, w1b.x, m21[0], m21[1]);
            mm3(vya, w1a.y, vyb, w1b.y, m21[2], m21[3]);
            mm3(vya, w2a.x, vyb, w2b.x, m22[0], m22[1]);
            mm3(vya, w2a.y, vyb, w2b.y, m22[2], m22[3]);
        }
    }

    // Cross-ci-half combine: v region is dead now; reuse as scratch.
    __syncthreads();   // everyone done reading s_v
    if (cihalf == 1) {
        uint4* dst = s_r + (cg*32 + px)*4;
        dst[0] = make_uint4(m11[0], m11[1], m11[2], m11[3]);
        dst[1] = make_uint4(m12[0], m12[1], m12[2], m12[3]);
        dst[2] = make_uint4(m21[0], m21[1], m21[2], m21[3]);
        dst[3] = make_uint4(m22[0], m22[1], m22[2], m22[3]);
    }
    __syncthreads();
    if (cihalf == 0 && px < WO) {
        const uint4* src = s_r + (cg*32 + px)*4;
        const uint4 o11 = src[0], o12 = src[1], o21 = src[2], o22 = src[3];
        m11[0] = umax(m11[0], o11.x); m11[1] = umax(m11[1], o11.y);
        m11[2] = umax(m11[2], o11.z); m11[3] = umax(m11[3], o11.w);
        m12[0] = umax(m12[0], o12.x); m12[1] = umax(m12[1], o12.y);
        m12[2] = umax(m12[2], o12.z); m12[3] = umax(m12[3], o12.w);
        m21[0] = umax(m21[0], o21.x); m21[1] = umax(m21[1], o21.y);
        m21[2] = umax(m21[2], o21.z); m21[3] = umax(m21[3], o21.w);
        m22[0] = umax(m22[0], o22.x); m22[1] = umax(m22[1], o22.y);
        m22[2] = umax(m22[2], o22.z); m22[3] = umax(m22[3], o22.w);

        const int q = (n*HO + ho)*WO + px;
        const float4 bv = *reinterpret_cast<const float4*>(bias + c0);
        float4 res;
        res.x = __uint_as_float(m11[0]) - __uint_as_float(m12[0])
              - __uint_as_float(m21[0]) + __uint_as_float(m22[0]) + bv.x;
        res.y = __uint_as_float(m11[1]) - __uint_as_float(m12[1])
              - __uint_as_float(m21[1]) + __uint_as_float(m22[1]) + bv.y;
        res.z = __uint_as_float(m11[2]) - __uint_as_float(m12[2])
              - __uint_as_float(m21[2]) + __uint_as_float(m22[2]) + bv.z;
        res.w = __uint_as_float(m11[3]) - __uint_as_float(m12[3])
              - __uint_as_float(m21[3]) + __uint_as_float(m22[3]) + bv.w;
        *reinterpret_cast<float4*>(out + (size_t)q*COUT + c0) = res;
    }
}

// ---------------------------------------------------------------------------
extern "C" void kernel_launch(void* const* d_in, const int* in_sizes, int n_in,
                              void* d_out, int out_size) {
    const float* x    = (const float*)d_in[0];
    const float* k1   = (const float*)d_in[1];
    const float* k2   = (const float*)d_in[2];
    const float* bias = (const float*)d_in[3];
    float* out = (float*)d_out;

    // Idempotent attribute set (host-side, not a stream op; capture-safe).
    cudaFuncSetAttribute(morph_main,
                         cudaFuncAttributeMaxDynamicSharedMemorySize,
                         SMEM_BYTES);

    prep<<<TBLOCKS + WBLOCKS, dim3(32,32)>>>(x, k1, k2);
    morph_main<<<HO*N_IMG*2, 512, SMEM_BYTES>>>(bias, out);
}